// round 1
// baseline (speedup 1.0000x reference)
#include <cuda_runtime.h>
#include <cuda_bf16.h>
#include <cstdint>
#include <cstdio>

// ---------------------------------------------------------------------------
// SimplePoolGCN: 3x (adj-aggregate GEMM -> linear GEMM + bias + BN stats ->
// BN+ReLU+group-mean-pool) + final FC.
// Shapes: B=256, N0=1024,N1=256,N2=64, IN=128,H0=256,H1=512,H2=1024,OUT=256.
// ---------------------------------------------------------------------------

#define BATCH 256
#define N0 1024
#define N1 256
#define N2 64
#define CIN 128
#define H0 256
#define H1 512
#define H2 1024
#define OUTD 256
#define BN_EPS 1e-5f

// Scratch (device globals; allocation at module load, allowed by harness rules)
__device__ float g_t[(size_t)BATCH * N0 * CIN];   // max aggregate buffer (33.5M)
__device__ float g_h[(size_t)BATCH * N0 * H0];    // max hidden buffer   (67M)
__device__ float g_p[(size_t)BATCH * N1 * H0];    // max pooled buffer   (16.7M)
__device__ float g_sum[1024];
__device__ float g_sumsq[1024];
__device__ float g_scale[1024];
__device__ float g_shift[1024];

// ---------------------------------------------------------------------------
// Big SIMT GEMM: C[b] = A[b] * B[b] (+bias) (+channel sum/sumsq stats)
// Row-major. BM=BN=128, BK=8, 256 threads, 8x8 per thread.
// Requires M%128==0, N%128==0, K%8==0.
// ---------------------------------------------------------------------------
__global__ __launch_bounds__(256)
void gemm128(const float* __restrict__ A, const float* __restrict__ Bm,
             float* __restrict__ C, int M, int N, int K,
             size_t sA, size_t sB, size_t sC,
             const float* __restrict__ bias,
             float* __restrict__ sumOut, float* __restrict__ sqOut)
{
    const int BM = 128, BN = 128, BK = 8;
    __shared__ float As[8][128];
    __shared__ float Bs[8][128];

    const int bz = blockIdx.z;
    const float* Ab = A + (size_t)bz * sA;
    const float* Bb = Bm + (size_t)bz * sB;
    float* Cb = C + (size_t)bz * sC;

    const int rowStart = blockIdx.y * BM;
    const int colStart = blockIdx.x * BN;
    const int tid = threadIdx.x;
    const int tx = tid & 15;        // column group (8 cols)
    const int ty = tid >> 4;        // row group (8 rows)

    // load mappings
    const int arow  = tid >> 1;          // 0..127
    const int acol4 = (tid & 1) * 4;     // 0 or 4
    const int brow  = tid >> 5;          // 0..7
    const int bcol4 = (tid & 31) * 4;    // 0..124

    float acc[8][8];
#pragma unroll
    for (int i = 0; i < 8; i++)
#pragma unroll
        for (int j = 0; j < 8; j++) acc[i][j] = 0.f;

    const float* Aptr = Ab + (size_t)(rowStart + arow) * K + acol4;
    const float* Bptr = Bb + (size_t)brow * N + colStart + bcol4;

    const int nk = K / BK;
    for (int kt = 0; kt < nk; ++kt) {
        float4 av = *(const float4*)Aptr;
        float4 bv = *(const float4*)Bptr;
        As[acol4 + 0][arow] = av.x;
        As[acol4 + 1][arow] = av.y;
        As[acol4 + 2][arow] = av.z;
        As[acol4 + 3][arow] = av.w;
        *(float4*)&Bs[brow][bcol4] = bv;
        __syncthreads();
#pragma unroll
        for (int k = 0; k < BK; k++) {
            float a[8], b[8];
            *(float4*)&a[0] = *(const float4*)&As[k][ty * 8];
            *(float4*)&a[4] = *(const float4*)&As[k][ty * 8 + 4];
            *(float4*)&b[0] = *(const float4*)&Bs[k][tx * 8];
            *(float4*)&b[4] = *(const float4*)&Bs[k][tx * 8 + 4];
#pragma unroll
            for (int i = 0; i < 8; i++)
#pragma unroll
                for (int j = 0; j < 8; j++)
                    acc[i][j] = fmaf(a[i], b[j], acc[i][j]);
        }
        __syncthreads();
        Aptr += BK;
        Bptr += (size_t)BK * N;
    }

    // epilogue: bias add + store
    float bj[8];
#pragma unroll
    for (int j = 0; j < 8; j++)
        bj[j] = bias ? bias[colStart + tx * 8 + j] : 0.f;

#pragma unroll
    for (int i = 0; i < 8; i++) {
#pragma unroll
        for (int j = 0; j < 8; j++) acc[i][j] += bj[j];
        size_t off = (size_t)(rowStart + ty * 8 + i) * N + colStart + tx * 8;
        *(float4*)&Cb[off]     = make_float4(acc[i][0], acc[i][1], acc[i][2], acc[i][3]);
        *(float4*)&Cb[off + 4] = make_float4(acc[i][4], acc[i][5], acc[i][6], acc[i][7]);
    }

    // optional per-channel stats (sum, sum^2) for BatchNorm, accumulated globally
    if (sumOut) {
        float* sred  = (float*)As;          // reuse smem: 128 floats
        float* sqred = sred + BN;           // next 128 floats
        if (tid < 2 * BN) sred[tid] = 0.f;  // 256 threads zero 256 floats
        __syncthreads();
#pragma unroll
        for (int j = 0; j < 8; j++) {
            float ps = 0.f, pq = 0.f;
#pragma unroll
            for (int i = 0; i < 8; i++) {
                float v = acc[i][j];
                ps += v;
                pq += v * v;
            }
            atomicAdd(&sred[tx * 8 + j], ps);
            atomicAdd(&sqred[tx * 8 + j], pq);
        }
        __syncthreads();
        if (tid < BN) {
            atomicAdd(&sumOut[colStart + tid], sred[tid]);
            atomicAdd(&sqOut[colStart + tid], sqred[tid]);
        }
    }
}

// ---------------------------------------------------------------------------
// Small GEMM: BM=BN=64, BK=16, 256 threads, 4x4 per thread (+bias).
// Requires M%64==0, N%64==0, K%16==0.
// ---------------------------------------------------------------------------
__global__ __launch_bounds__(256)
void gemm64(const float* __restrict__ A, const float* __restrict__ Bm,
            float* __restrict__ C, int M, int N, int K,
            size_t sA, size_t sB, size_t sC,
            const float* __restrict__ bias)
{
    const int BK = 16;
    __shared__ float As[16][64];
    __shared__ float Bs[16][64];

    const int bz = blockIdx.z;
    const float* Ab = A + (size_t)bz * sA;
    const float* Bb = Bm + (size_t)bz * sB;
    float* Cb = C + (size_t)bz * sC;

    const int rowStart = blockIdx.y * 64;
    const int colStart = blockIdx.x * 64;
    const int tid = threadIdx.x;
    const int tx = tid & 15;
    const int ty = tid >> 4;

    const int arow  = tid >> 2;          // 0..63
    const int acol4 = (tid & 3) * 4;     // 0..12
    const int brow  = tid >> 4;          // 0..15
    const int bcol4 = (tid & 15) * 4;    // 0..60

    float acc[4][4];
#pragma unroll
    for (int i = 0; i < 4; i++)
#pragma unroll
        for (int j = 0; j < 4; j++) acc[i][j] = 0.f;

    const float* Aptr = Ab + (size_t)(rowStart + arow) * K + acol4;
    const float* Bptr = Bb + (size_t)brow * N + colStart + bcol4;

    const int nk = K / BK;
    for (int kt = 0; kt < nk; ++kt) {
        float4 av = *(const float4*)Aptr;
        float4 bv = *(const float4*)Bptr;
        As[acol4 + 0][arow] = av.x;
        As[acol4 + 1][arow] = av.y;
        As[acol4 + 2][arow] = av.z;
        As[acol4 + 3][arow] = av.w;
        *(float4*)&Bs[brow][bcol4] = bv;
        __syncthreads();
#pragma unroll
        for (int k = 0; k < BK; k++) {
            float a[4], b[4];
            *(float4*)&a[0] = *(const float4*)&As[k][ty * 4];
            *(float4*)&b[0] = *(const float4*)&Bs[k][tx * 4];
#pragma unroll
            for (int i = 0; i < 4; i++)
#pragma unroll
                for (int j = 0; j < 4; j++)
                    acc[i][j] = fmaf(a[i], b[j], acc[i][j]);
        }
        __syncthreads();
        Aptr += BK;
        Bptr += (size_t)BK * N;
    }

    float bj[4];
#pragma unroll
    for (int j = 0; j < 4; j++)
        bj[j] = bias ? bias[colStart + tx * 4 + j] : 0.f;
#pragma unroll
    for (int i = 0; i < 4; i++) {
        size_t off = (size_t)(rowStart + ty * 4 + i) * N + colStart + tx * 4;
        *(float4*)&Cb[off] = make_float4(acc[i][0] + bj[0], acc[i][1] + bj[1],
                                         acc[i][2] + bj[2], acc[i][3] + bj[3]);
    }
}

// ---------------------------------------------------------------------------
// BN stat helpers
// ---------------------------------------------------------------------------
__global__ void zero_stats()
{
    int c = blockIdx.x * blockDim.x + threadIdx.x;
    if (c < 1024) { g_sum[c] = 0.f; g_sumsq[c] = 0.f; }
}

__global__ void finalize_stats(const float* __restrict__ gamma,
                               const float* __restrict__ beta,
                               int C, float invn)
{
    int c = blockIdx.x * blockDim.x + threadIdx.x;
    if (c < C) {
        float m  = g_sum[c] * invn;
        float v  = g_sumsq[c] * invn - m * m;
        float sc = gamma[c] * rsqrtf(v + BN_EPS);
        g_scale[c] = sc;
        g_shift[c] = beta[c] - m * sc;
    }
}

// ---------------------------------------------------------------------------
// Fused BN(affine) + ReLU + group-mean-pool.
// h: [B, Nin, C]; nm: [Mout, G]; out: [B, Mout, C]
// ---------------------------------------------------------------------------
__global__ void bn_relu_pool(const float* __restrict__ h,
                             const int* __restrict__ nm,
                             float* __restrict__ out,
                             int Bb, int Mout, int C, int G, int Nin)
{
    long long idx = (long long)blockIdx.x * blockDim.x + threadIdx.x;
    long long total = (long long)Bb * Mout * C;
    if (idx >= total) return;
    int c = (int)(idx % C);
    long long t = idx / C;
    int m = (int)(t % Mout);
    int b = (int)(t / Mout);
    float sc = g_scale[c];
    float sh = g_shift[c];
    float s = 0.f;
    for (int g2 = 0; g2 < G; ++g2) {
        int node = nm[m * G + g2];
        float v = fmaf(h[((size_t)b * Nin + node) * C + c], sc, sh);
        s += fmaxf(v, 0.f);
    }
    out[idx] = s * (1.f / (float)G);
}

// ---------------------------------------------------------------------------
// Launch
// ---------------------------------------------------------------------------
extern "C" void kernel_launch(void* const* d_in, const int* in_sizes, int n_in,
                              void* d_out, int out_size)
{
    (void)in_sizes; (void)n_in; (void)out_size;
    const float* x    = (const float*)d_in[0];
    const float* adj0 = (const float*)d_in[1];
    const float* adj1 = (const float*)d_in[2];
    const float* adj2 = (const float*)d_in[3];
    const int*   nm0  = (const int*)d_in[4];
    const int*   nm1  = (const int*)d_in[5];
    const int*   nm2  = (const int*)d_in[6];
    const float* W0   = (const float*)d_in[7];
    const float* b0   = (const float*)d_in[8];
    const float* gg0  = (const float*)d_in[9];
    const float* be0  = (const float*)d_in[10];
    const float* W1   = (const float*)d_in[11];
    const float* b1   = (const float*)d_in[12];
    const float* gg1  = (const float*)d_in[13];
    const float* be1  = (const float*)d_in[14];
    const float* W2   = (const float*)d_in[15];
    const float* b2   = (const float*)d_in[16];
    const float* gg2  = (const float*)d_in[17];
    const float* be2  = (const float*)d_in[18];
    const float* fcW  = (const float*)d_in[19];
    const float* fcb  = (const float*)d_in[20];
    float* out = (float*)d_out;

    float *pt, *ph, *pp, *psum, *psq;
    cudaGetSymbolAddress((void**)&pt, g_t);
    cudaGetSymbolAddress((void**)&ph, g_h);
    cudaGetSymbolAddress((void**)&pp, g_p);
    cudaGetSymbolAddress((void**)&psum, g_sum);
    cudaGetSymbolAddress((void**)&psq, g_sumsq);

    // ---------------- Block 0 ----------------
    // t = adj0 @ x : per-batch [1024x1024] x [1024x128]
    gemm128<<<dim3(CIN / 128, N0 / 128, BATCH), 256>>>(
        adj0, x, pt, N0, CIN, N0,
        0, (size_t)N0 * CIN, (size_t)N0 * CIN, nullptr, nullptr, nullptr);
    // h = t @ W0 + b0  (one big GEMM over B*N0 rows) + BN stats
    zero_stats<<<4, 256>>>();
    gemm128<<<dim3(H0 / 128, (BATCH * N0) / 128, 1), 256>>>(
        pt, W0, ph, BATCH * N0, H0, CIN, 0, 0, 0, b0, psum, psq);
    finalize_stats<<<(H0 + 255) / 256, 256>>>(gg0, be0, H0, 1.f / ((float)BATCH * N0));
    {
        long long total = (long long)BATCH * N1 * H0;
        bn_relu_pool<<<(unsigned)((total + 255) / 256), 256>>>(ph, nm0, pp, BATCH, N1, H0, 4, N0);
    }

    // ---------------- Block 1 ----------------
    gemm128<<<dim3(H0 / 128, N1 / 128, BATCH), 256>>>(
        adj1, pp, pt, N1, H0, N1,
        0, (size_t)N1 * H0, (size_t)N1 * H0, nullptr, nullptr, nullptr);
    zero_stats<<<4, 256>>>();
    gemm128<<<dim3(H1 / 128, (BATCH * N1) / 128, 1), 256>>>(
        pt, W1, ph, BATCH * N1, H1, H0, 0, 0, 0, b1, psum, psq);
    finalize_stats<<<(H1 + 255) / 256, 256>>>(gg1, be1, H1, 1.f / ((float)BATCH * N1));
    {
        long long total = (long long)BATCH * N2 * H1;
        bn_relu_pool<<<(unsigned)((total + 255) / 256), 256>>>(ph, nm1, pp, BATCH, N2, H1, 4, N1);
    }

    // ---------------- Block 2 ----------------
    // t = adj2 @ c1d : per-batch [64x64] x [64x512] -> small tile config
    gemm64<<<dim3(H1 / 64, N2 / 64, BATCH), 256>>>(
        adj2, pp, pt, N2, H1, N2,
        0, (size_t)N2 * H1, (size_t)N2 * H1, nullptr);
    zero_stats<<<4, 256>>>();
    gemm128<<<dim3(H2 / 128, (BATCH * N2) / 128, 1), 256>>>(
        pt, W2, ph, BATCH * N2, H2, H1, 0, 0, 0, b2, psum, psq);
    finalize_stats<<<(H2 + 255) / 256, 256>>>(gg2, be2, H2, 1.f / ((float)BATCH * N2));
    {
        // pool over all 64 nodes -> [B, 1, 1024] stored as [B, 1024]
        long long total = (long long)BATCH * 1 * H2;
        bn_relu_pool<<<(unsigned)((total + 255) / 256), 256>>>(ph, nm2, pp, BATCH, 1, H2, 64, N2);
    }

    // ---------------- FC ----------------
    // out = c2d @ fcW + fcb : [256 x 1024] x [1024 x 256]
    gemm64<<<dim3(OUTD / 64, BATCH / 64, 1), 256>>>(
        pp, fcW, out, BATCH, OUTD, H2, 0, 0, 0, fcb);
}

// round 2
// speedup vs baseline: 1.0021x; 1.0021x over previous
#include <cuda_runtime.h>
#include <cuda_bf16.h>
#include <cstdint>
#include <cstdio>

// ---------------------------------------------------------------------------
// SimplePoolGCN: 3x (adj-aggregate GEMM -> linear GEMM + bias + BN stats ->
// BN+ReLU+group-mean-pool) + final FC.
// Shapes: B=256, N0=1024,N1=256,N2=64, IN=128,H0=256,H1=512,H2=1024,OUT=256.
// ---------------------------------------------------------------------------

#define BATCH 256
#define N0 1024
#define N1 256
#define N2 64
#define CIN 128
#define H0 256
#define H1 512
#define H2 1024
#define OUTD 256
#define BN_EPS 1e-5f

// Scratch (device globals; allocation at module load, allowed by harness rules)
__device__ float g_t[(size_t)BATCH * N0 * CIN];   // max aggregate buffer (33.5M)
__device__ float g_h[(size_t)BATCH * N0 * H0];    // max hidden buffer   (67M)
__device__ float g_p[(size_t)BATCH * N1 * H0];    // max pooled buffer   (16.7M)
__device__ float g_sum[1024];
__device__ float g_sumsq[1024];
__device__ float g_scale[1024];
__device__ float g_shift[1024];

// ---------------------------------------------------------------------------
// Big SIMT GEMM: C[b] = A[b] * B[b] (+bias) (+channel sum/sumsq stats)
// Row-major. BM=BN=128, BK=8, 256 threads, 8x8 per thread.
// Requires M%128==0, N%128==0, K%8==0.
// ---------------------------------------------------------------------------
__global__ __launch_bounds__(256)
void gemm128(const float* __restrict__ A, const float* __restrict__ Bm,
             float* __restrict__ C, int M, int N, int K,
             size_t sA, size_t sB, size_t sC,
             const float* __restrict__ bias,
             float* __restrict__ sumOut, float* __restrict__ sqOut)
{
    const int BM = 128, BN = 128, BK = 8;
    __shared__ float As[8][128];
    __shared__ float Bs[8][128];

    const int bz = blockIdx.z;
    const float* Ab = A + (size_t)bz * sA;
    const float* Bb = Bm + (size_t)bz * sB;
    float* Cb = C + (size_t)bz * sC;

    const int rowStart = blockIdx.y * BM;
    const int colStart = blockIdx.x * BN;
    const int tid = threadIdx.x;
    const int tx = tid & 15;        // column group (8 cols)
    const int ty = tid >> 4;        // row group (8 rows)

    // load mappings
    const int arow  = tid >> 1;          // 0..127
    const int acol4 = (tid & 1) * 4;     // 0 or 4
    const int brow  = tid >> 5;          // 0..7
    const int bcol4 = (tid & 31) * 4;    // 0..124

    float acc[8][8];
#pragma unroll
    for (int i = 0; i < 8; i++)
#pragma unroll
        for (int j = 0; j < 8; j++) acc[i][j] = 0.f;

    const float* Aptr = Ab + (size_t)(rowStart + arow) * K + acol4;
    const float* Bptr = Bb + (size_t)brow * N + colStart + bcol4;

    const int nk = K / BK;
    for (int kt = 0; kt < nk; ++kt) {
        float4 av = *(const float4*)Aptr;
        float4 bv = *(const float4*)Bptr;
        As[acol4 + 0][arow] = av.x;
        As[acol4 + 1][arow] = av.y;
        As[acol4 + 2][arow] = av.z;
        As[acol4 + 3][arow] = av.w;
        *(float4*)&Bs[brow][bcol4] = bv;
        __syncthreads();
#pragma unroll
        for (int k = 0; k < BK; k++) {
            float a[8], b[8];
            *(float4*)&a[0] = *(const float4*)&As[k][ty * 8];
            *(float4*)&a[4] = *(const float4*)&As[k][ty * 8 + 4];
            *(float4*)&b[0] = *(const float4*)&Bs[k][tx * 8];
            *(float4*)&b[4] = *(const float4*)&Bs[k][tx * 8 + 4];
#pragma unroll
            for (int i = 0; i < 8; i++)
#pragma unroll
                for (int j = 0; j < 8; j++)
                    acc[i][j] = fmaf(a[i], b[j], acc[i][j]);
        }
        __syncthreads();
        Aptr += BK;
        Bptr += (size_t)BK * N;
    }

    // epilogue: bias add + store
    float bj[8];
#pragma unroll
    for (int j = 0; j < 8; j++)
        bj[j] = bias ? bias[colStart + tx * 8 + j] : 0.f;

#pragma unroll
    for (int i = 0; i < 8; i++) {
#pragma unroll
        for (int j = 0; j < 8; j++) acc[i][j] += bj[j];
        size_t off = (size_t)(rowStart + ty * 8 + i) * N + colStart + tx * 8;
        *(float4*)&Cb[off]     = make_float4(acc[i][0], acc[i][1], acc[i][2], acc[i][3]);
        *(float4*)&Cb[off + 4] = make_float4(acc[i][4], acc[i][5], acc[i][6], acc[i][7]);
    }

    // optional per-channel stats (sum, sum^2) for BatchNorm, accumulated globally
    if (sumOut) {
        float* sred  = (float*)As;          // reuse smem: 128 floats
        float* sqred = sred + BN;           // next 128 floats
        if (tid < 2 * BN) sred[tid] = 0.f;  // 256 threads zero 256 floats
        __syncthreads();
#pragma unroll
        for (int j = 0; j < 8; j++) {
            float ps = 0.f, pq = 0.f;
#pragma unroll
            for (int i = 0; i < 8; i++) {
                float v = acc[i][j];
                ps += v;
                pq += v * v;
            }
            atomicAdd(&sred[tx * 8 + j], ps);
            atomicAdd(&sqred[tx * 8 + j], pq);
        }
        __syncthreads();
        if (tid < BN) {
            atomicAdd(&sumOut[colStart + tid], sred[tid]);
            atomicAdd(&sqOut[colStart + tid], sqred[tid]);
        }
    }
}

// ---------------------------------------------------------------------------
// Small GEMM: BM=BN=64, BK=16, 256 threads, 4x4 per thread (+bias).
// Requires M%64==0, N%64==0, K%16==0.
// ---------------------------------------------------------------------------
__global__ __launch_bounds__(256)
void gemm64(const float* __restrict__ A, const float* __restrict__ Bm,
            float* __restrict__ C, int M, int N, int K,
            size_t sA, size_t sB, size_t sC,
            const float* __restrict__ bias)
{
    const int BK = 16;
    __shared__ float As[16][64];
    __shared__ float Bs[16][64];

    const int bz = blockIdx.z;
    const float* Ab = A + (size_t)bz * sA;
    const float* Bb = Bm + (size_t)bz * sB;
    float* Cb = C + (size_t)bz * sC;

    const int rowStart = blockIdx.y * 64;
    const int colStart = blockIdx.x * 64;
    const int tid = threadIdx.x;
    const int tx = tid & 15;
    const int ty = tid >> 4;

    const int arow  = tid >> 2;          // 0..63
    const int acol4 = (tid & 3) * 4;     // 0..12
    const int brow  = tid >> 4;          // 0..15
    const int bcol4 = (tid & 15) * 4;    // 0..60

    float acc[4][4];
#pragma unroll
    for (int i = 0; i < 4; i++)
#pragma unroll
        for (int j = 0; j < 4; j++) acc[i][j] = 0.f;

    const float* Aptr = Ab + (size_t)(rowStart + arow) * K + acol4;
    const float* Bptr = Bb + (size_t)brow * N + colStart + bcol4;

    const int nk = K / BK;
    for (int kt = 0; kt < nk; ++kt) {
        float4 av = *(const float4*)Aptr;
        float4 bv = *(const float4*)Bptr;
        As[acol4 + 0][arow] = av.x;
        As[acol4 + 1][arow] = av.y;
        As[acol4 + 2][arow] = av.z;
        As[acol4 + 3][arow] = av.w;
        *(float4*)&Bs[brow][bcol4] = bv;
        __syncthreads();
#pragma unroll
        for (int k = 0; k < BK; k++) {
            float a[4], b[4];
            *(float4*)&a[0] = *(const float4*)&As[k][ty * 4];
            *(float4*)&b[0] = *(const float4*)&Bs[k][tx * 4];
#pragma unroll
            for (int i = 0; i < 4; i++)
#pragma unroll
                for (int j = 0; j < 4; j++)
                    acc[i][j] = fmaf(a[i], b[j], acc[i][j]);
        }
        __syncthreads();
        Aptr += BK;
        Bptr += (size_t)BK * N;
    }

    float bj[4];
#pragma unroll
    for (int j = 0; j < 4; j++)
        bj[j] = bias ? bias[colStart + tx * 4 + j] : 0.f;
#pragma unroll
    for (int i = 0; i < 4; i++) {
        size_t off = (size_t)(rowStart + ty * 4 + i) * N + colStart + tx * 4;
        *(float4*)&Cb[off] = make_float4(acc[i][0] + bj[0], acc[i][1] + bj[1],
                                         acc[i][2] + bj[2], acc[i][3] + bj[3]);
    }
}

// ---------------------------------------------------------------------------
// BN stat helpers
// ---------------------------------------------------------------------------
__global__ void zero_stats()
{
    int c = blockIdx.x * blockDim.x + threadIdx.x;
    if (c < 1024) { g_sum[c] = 0.f; g_sumsq[c] = 0.f; }
}

__global__ void finalize_stats(const float* __restrict__ gamma,
                               const float* __restrict__ beta,
                               int C, float invn)
{
    int c = blockIdx.x * blockDim.x + threadIdx.x;
    if (c < C) {
        float m  = g_sum[c] * invn;
        float v  = g_sumsq[c] * invn - m * m;
        float sc = gamma[c] * rsqrtf(v + BN_EPS);
        g_scale[c] = sc;
        g_shift[c] = beta[c] - m * sc;
    }
}

// ---------------------------------------------------------------------------
// Fused BN(affine) + ReLU + group-mean-pool.
// h: [B, Nin, C]; nm: [Mout, G]; out: [B, Mout, C]
// ---------------------------------------------------------------------------
__global__ void bn_relu_pool(const float* __restrict__ h,
                             const int* __restrict__ nm,
                             float* __restrict__ out,
                             int Bb, int Mout, int C, int G, int Nin)
{
    long long idx = (long long)blockIdx.x * blockDim.x + threadIdx.x;
    long long total = (long long)Bb * Mout * C;
    if (idx >= total) return;
    int c = (int)(idx % C);
    long long t = idx / C;
    int m = (int)(t % Mout);
    int b = (int)(t / Mout);
    float sc = g_scale[c];
    float sh = g_shift[c];
    float s = 0.f;
    for (int g2 = 0; g2 < G; ++g2) {
        int node = nm[m * G + g2];
        float v = fmaf(h[((size_t)b * Nin + node) * C + c], sc, sh);
        s += fmaxf(v, 0.f);
    }
    out[idx] = s * (1.f / (float)G);
}

// ---------------------------------------------------------------------------
// Launch
// ---------------------------------------------------------------------------
extern "C" void kernel_launch(void* const* d_in, const int* in_sizes, int n_in,
                              void* d_out, int out_size)
{
    (void)in_sizes; (void)n_in; (void)out_size;
    const float* x    = (const float*)d_in[0];
    const float* adj0 = (const float*)d_in[1];
    const float* adj1 = (const float*)d_in[2];
    const float* adj2 = (const float*)d_in[3];
    const int*   nm0  = (const int*)d_in[4];
    const int*   nm1  = (const int*)d_in[5];
    const int*   nm2  = (const int*)d_in[6];
    const float* W0   = (const float*)d_in[7];
    const float* b0   = (const float*)d_in[8];
    const float* gg0  = (const float*)d_in[9];
    const float* be0  = (const float*)d_in[10];
    const float* W1   = (const float*)d_in[11];
    const float* b1   = (const float*)d_in[12];
    const float* gg1  = (const float*)d_in[13];
    const float* be1  = (const float*)d_in[14];
    const float* W2   = (const float*)d_in[15];
    const float* b2   = (const float*)d_in[16];
    const float* gg2  = (const float*)d_in[17];
    const float* be2  = (const float*)d_in[18];
    const float* fcW  = (const float*)d_in[19];
    const float* fcb  = (const float*)d_in[20];
    float* out = (float*)d_out;

    float *pt, *ph, *pp, *psum, *psq;
    cudaGetSymbolAddress((void**)&pt, g_t);
    cudaGetSymbolAddress((void**)&ph, g_h);
    cudaGetSymbolAddress((void**)&pp, g_p);
    cudaGetSymbolAddress((void**)&psum, g_sum);
    cudaGetSymbolAddress((void**)&psq, g_sumsq);

    // ---------------- Block 0 ----------------
    // t = adj0 @ x : per-batch [1024x1024] x [1024x128]
    gemm128<<<dim3(CIN / 128, N0 / 128, BATCH), 256>>>(
        adj0, x, pt, N0, CIN, N0,
        0, (size_t)N0 * CIN, (size_t)N0 * CIN, nullptr, nullptr, nullptr);
    // h = t @ W0 + b0  (one big GEMM over B*N0 rows) + BN stats
    zero_stats<<<4, 256>>>();
    gemm128<<<dim3(H0 / 128, (BATCH * N0) / 128, 1), 256>>>(
        pt, W0, ph, BATCH * N0, H0, CIN, 0, 0, 0, b0, psum, psq);
    finalize_stats<<<(H0 + 255) / 256, 256>>>(gg0, be0, H0, 1.f / ((float)BATCH * N0));
    {
        long long total = (long long)BATCH * N1 * H0;
        bn_relu_pool<<<(unsigned)((total + 255) / 256), 256>>>(ph, nm0, pp, BATCH, N1, H0, 4, N0);
    }

    // ---------------- Block 1 ----------------
    gemm128<<<dim3(H0 / 128, N1 / 128, BATCH), 256>>>(
        adj1, pp, pt, N1, H0, N1,
        0, (size_t)N1 * H0, (size_t)N1 * H0, nullptr, nullptr, nullptr);
    zero_stats<<<4, 256>>>();
    gemm128<<<dim3(H1 / 128, (BATCH * N1) / 128, 1), 256>>>(
        pt, W1, ph, BATCH * N1, H1, H0, 0, 0, 0, b1, psum, psq);
    finalize_stats<<<(H1 + 255) / 256, 256>>>(gg1, be1, H1, 1.f / ((float)BATCH * N1));
    {
        long long total = (long long)BATCH * N2 * H1;
        bn_relu_pool<<<(unsigned)((total + 255) / 256), 256>>>(ph, nm1, pp, BATCH, N2, H1, 4, N1);
    }

    // ---------------- Block 2 ----------------
    // t = adj2 @ c1d : per-batch [64x64] x [64x512] -> small tile config
    gemm64<<<dim3(H1 / 64, N2 / 64, BATCH), 256>>>(
        adj2, pp, pt, N2, H1, N2,
        0, (size_t)N2 * H1, (size_t)N2 * H1, nullptr);
    zero_stats<<<4, 256>>>();
    gemm128<<<dim3(H2 / 128, (BATCH * N2) / 128, 1), 256>>>(
        pt, W2, ph, BATCH * N2, H2, H1, 0, 0, 0, b2, psum, psq);
    finalize_stats<<<(H2 + 255) / 256, 256>>>(gg2, be2, H2, 1.f / ((float)BATCH * N2));
    {
        // pool over all 64 nodes -> [B, 1, 1024] stored as [B, 1024]
        long long total = (long long)BATCH * 1 * H2;
        bn_relu_pool<<<(unsigned)((total + 255) / 256), 256>>>(ph, nm2, pp, BATCH, 1, H2, 64, N2);
    }

    // ---------------- FC ----------------
    // out = c2d @ fcW + fcb : [256 x 1024] x [1024 x 256]
    gemm64<<<dim3(OUTD / 64, BATCH / 64, 1), 256>>>(
        pp, fcW, out, BATCH, OUTD, H2, 0, 0, 0, fcb);
}